// round 1
// baseline (speedup 1.0000x reference)
#include <cuda_runtime.h>
#include <cuda_bf16.h>

// SamplePDF: inverse-transform sampling.
//   bins   : [N, 64]  sorted bin edges
//   weights: [N, 63]
//   u      : [N, 128] uniform samples
//   out    : [N, 128] samples
//
// Strategy: one warp per ray. Warp-shuffle inclusive scan builds the 64-entry
// CDF; CDF + bins staged in shared memory (per-warp 512 B); each lane handles
// 4 of the 128 samples with a branchless 6-step lower_bound. All global
// traffic (weights, bins, u, out) is coalesced -> HBM-bound streaming kernel.

#define N_BINS 64          // bin edges per ray (cdf length == 64)
#define N_W    63          // weights per ray
#define N_IMP  128         // samples per ray
#define WARPS_PER_BLOCK 8
#define THREADS (WARPS_PER_BLOCK * 32)

__global__ __launch_bounds__(THREADS)
void sample_pdf_kernel(const float* __restrict__ bins,
                       const float* __restrict__ weights,
                       const float* __restrict__ u,
                       float* __restrict__ out,
                       int n_rays)
{
    __shared__ float s_cdf [WARPS_PER_BLOCK][N_BINS];
    __shared__ float s_bins[WARPS_PER_BLOCK][N_BINS];

    const int warp = threadIdx.x >> 5;
    const int lane = threadIdx.x & 31;
    const int ray  = blockIdx.x * WARPS_PER_BLOCK + warp;
    if (ray >= n_rays) return;

    // ---- load weights (coalesced), add 1e-5 -------------------------------
    const float* wrow = weights + (long long)ray * N_W;
    float v0 = wrow[lane] + 1e-5f;                        // idx = lane (0..31)
    float v1 = (lane < N_W - 32) ? wrow[lane + 32] + 1e-5f : 0.0f; // idx 32..62

    // ---- warp inclusive scans --------------------------------------------
    float s0 = v0;
    #pragma unroll
    for (int d = 1; d < 32; d <<= 1) {
        float t = __shfl_up_sync(0xffffffffu, s0, d);
        if (lane >= d) s0 += t;
    }
    float s1 = v1;
    #pragma unroll
    for (int d = 1; d < 32; d <<= 1) {
        float t = __shfl_up_sync(0xffffffffu, s1, d);
        if (lane >= d) s1 += t;
    }
    const float sum0  = __shfl_sync(0xffffffffu, s0, 31);   // sum w[0..31]
    const float total = sum0 + __shfl_sync(0xffffffffu, s1, 31);
    const float inv   = 1.0f / total;

    // ---- build cdf in shared: cdf[0]=0, cdf[j]=prefix(j)/total -----------
    if (lane == 0) s_cdf[warp][0] = 0.0f;
    s_cdf[warp][lane + 1] = s0 * inv;                       // cdf[1..32]
    if (lane < N_W - 32)
        s_cdf[warp][lane + 33] = (sum0 + s1) * inv;         // cdf[33..63]

    // ---- stage bins in shared (coalesced loads) ---------------------------
    const float* brow = bins + (long long)ray * N_BINS;
    s_bins[warp][lane]      = brow[lane];
    s_bins[warp][lane + 32] = brow[lane + 32];

    __syncwarp();

    const float* cdf = s_cdf[warp];
    const float* bn  = s_bins[warp];
    const float* urow = u   + (long long)ray * N_IMP;
    float*       orow = out + (long long)ray * N_IMP;

    // ---- 128 samples, 4 per lane, coalesced -------------------------------
    #pragma unroll
    for (int k = 0; k < N_IMP / 32; ++k) {
        const float uv = urow[lane + 32 * k];

        // branchless lower_bound: largest idx with cdf[idx] < uv (idx>=0)
        int idx = 0;
        #pragma unroll
        for (int step = 32; step > 0; step >>= 1) {
            int probe = idx + step;
            if (probe < N_BINS && cdf[probe] < uv) idx = probe;
        }
        // searchsorted 'left' result j = idx+1 (or 0 if uv<=cdf[0]=0, in which
        // case u-cdf_lo == 0 and the result is bins[0] either way).
        const int lo = idx;
        const int hi = (idx + 1 < N_BINS) ? idx + 1 : N_BINS - 1;

        const float cdf_lo = cdf[lo];
        const float cdf_hi = cdf[hi];
        const float b_lo   = bn[lo];
        const float b_hi   = bn[hi];

        float denom = cdf_hi - cdf_lo;
        denom = (denom < 1e-5f) ? 1.0f : denom;
        const float t = (uv - cdf_lo) / denom;
        orow[lane + 32 * k] = fmaf(t, b_hi - b_lo, b_lo);
    }
}

extern "C" void kernel_launch(void* const* d_in, const int* in_sizes, int n_in,
                              void* d_out, int out_size)
{
    const float* bins    = (const float*)d_in[0];
    const float* weights = (const float*)d_in[1];
    const float* u       = (const float*)d_in[2];
    float* out = (float*)d_out;

    const int n_rays = in_sizes[0] / N_BINS;
    const int grid   = (n_rays + WARPS_PER_BLOCK - 1) / WARPS_PER_BLOCK;
    sample_pdf_kernel<<<grid, THREADS>>>(bins, weights, u, out, n_rays);
}

// round 2
// speedup vs baseline: 1.1781x; 1.1781x over previous
#include <cuda_runtime.h>
#include <cuda_bf16.h>

// SamplePDF: inverse-transform sampling, one warp per ray.
//   bins   : [N, 64]  sorted bin edges (rows 256B-aligned)
//   weights: [N, 63]
//   u      : [N, 128]
//   out    : [N, 128]
//
// R2: shared-memory-bound fix. Search levels 32/16/8 use warp-uniform
// registers (no LDS); bisection tracks cdf_lo/cdf_hi in registers so only
// bins need gathering. LDS per sample: 3 probes + 2 gathers (was 10).

#define N_BINS 64
#define N_W    63
#define N_IMP  128
#define WARPS_PER_BLOCK 8
#define THREADS (WARPS_PER_BLOCK * 32)

__global__ __launch_bounds__(THREADS)
void sample_pdf_kernel(const float* __restrict__ bins,
                       const float* __restrict__ weights,
                       const float* __restrict__ u,
                       float* __restrict__ out,
                       int n_rays)
{
    __shared__ float s_cdf [WARPS_PER_BLOCK][N_BINS];
    __shared__ float s_bins[WARPS_PER_BLOCK][N_BINS];

    const int warp = threadIdx.x >> 5;
    const int lane = threadIdx.x & 31;
    const int ray  = blockIdx.x * WARPS_PER_BLOCK + warp;
    if (ray >= n_rays) return;

    // ---- load weights as pairs: lane owns w[2l], w[2l+1] ------------------
    const float* wrow = weights + (long long)ray * N_W;
    const int l2 = lane * 2;
    const float wa = wrow[l2] + 1e-5f;                               // l2 <= 62
    const float wb = (l2 + 1 < N_W) ? wrow[l2 + 1] + 1e-5f : 0.0f;

    // ---- single 32-wide inclusive scan of pair sums -----------------------
    float P = wa + wb;
    #pragma unroll
    for (int d = 1; d < 32; d <<= 1) {
        float t = __shfl_up_sync(0xffffffffu, P, d);
        if (lane >= d) P += t;
    }
    const float total = __shfl_sync(0xffffffffu, P, 31);
    const float inv   = 1.0f / total;

    // warp-uniform CDF values for search levels 32/16/8 (all even indices:
    // cdf[2k+2] = P[k]*inv)
    const float cdf8  = __shfl_sync(0xffffffffu, P,  3) * inv;
    const float cdf16 = __shfl_sync(0xffffffffu, P,  7) * inv;
    const float cdf24 = __shfl_sync(0xffffffffu, P, 11) * inv;
    const float cdf32 = __shfl_sync(0xffffffffu, P, 15) * inv;
    const float cdf40 = __shfl_sync(0xffffffffu, P, 19) * inv;
    const float cdf48 = __shfl_sync(0xffffffffu, P, 23) * inv;
    const float cdf56 = __shfl_sync(0xffffffffu, P, 27) * inv;
    const float cdf63 = total * inv;   // == cdf[63] (rounding included)

    // ---- build cdf in shared: cdf[2l+1]=(P-wb)*inv, cdf[2l+2]=P*inv ------
    float* cdfw = s_cdf[warp];
    if (lane == 0) cdfw[0] = 0.0f;
    cdfw[l2 + 1] = (P - wb) * inv;
    if (l2 + 2 < N_BINS) cdfw[l2 + 2] = P * inv;

    // ---- stage bins (rows are 256B aligned -> float2 loads/stores) --------
    float* bnw = s_bins[warp];
    const float2 bv = ((const float2*)(bins + (long long)ray * N_BINS))[lane];
    ((float2*)bnw)[lane] = bv;

    __syncwarp();

    // ---- 4 samples per lane via one float4 load/store ---------------------
    const float4 uv4 = ((const float4*)(u + (long long)ray * N_IMP))[lane];
    float res[4];
    const float uvs[4] = {uv4.x, uv4.y, uv4.z, uv4.w};

    #pragma unroll
    for (int k = 0; k < 4; ++k) {
        const float uv = uvs[k];
        int   idx = 0;
        float lov = 0.0f;
        float hiv = cdf63;

        // level 32 (register)
        const bool c1 = cdf32 < uv;
        if (c1) { idx = 32; lov = cdf32; } else { hiv = cdf32; }
        // level 16 (register)
        const float p2 = c1 ? cdf48 : cdf16;
        const bool  c2 = p2 < uv;
        if (c2) { idx += 16; lov = p2; } else { hiv = p2; }
        // level 8 (register)
        const float p3 = c1 ? (c2 ? cdf56 : cdf40) : (c2 ? cdf24 : cdf8);
        const bool  c3 = p3 < uv;
        if (c3) { idx += 8; lov = p3; } else { hiv = p3; }

        // levels 4/2/1 (shared probes; idx+step <= 63 always)
        #pragma unroll
        for (int step = 4; step > 0; step >>= 1) {
            const float v = cdfw[idx + step];
            if (v < uv) { idx += step; lov = v; } else { hiv = v; }
        }
        // invariant: lov = cdf[idx], hiv = cdf[idx+1] (or cdf63 if idx==63)

        const int hi = (idx + 1 < N_BINS) ? idx + 1 : N_BINS - 1;
        const float blo = bnw[idx];
        const float bhi = bnw[hi];

        float denom = hiv - lov;
        denom = (denom < 1e-5f) ? 1.0f : denom;
        const float t = (uv - lov) / denom;
        res[k] = fmaf(t, bhi - blo, blo);
    }

    float4 o;
    o.x = res[0]; o.y = res[1]; o.z = res[2]; o.w = res[3];
    ((float4*)(out + (long long)ray * N_IMP))[lane] = o;
}

extern "C" void kernel_launch(void* const* d_in, const int* in_sizes, int n_in,
                              void* d_out, int out_size)
{
    const float* bins    = (const float*)d_in[0];
    const float* weights = (const float*)d_in[1];
    const float* u       = (const float*)d_in[2];
    float* out = (float*)d_out;

    const int n_rays = in_sizes[0] / N_BINS;
    const int grid   = (n_rays + WARPS_PER_BLOCK - 1) / WARPS_PER_BLOCK;
    sample_pdf_kernel<<<grid, THREADS>>>(bins, weights, u, out, n_rays);
}

// round 3
// speedup vs baseline: 1.3461x; 1.1426x over previous
#include <cuda_runtime.h>
#include <cuda_bf16.h>

// SamplePDF: inverse-transform sampling, one warp per ray.
//   bins   : [N, 64]  sorted bin edges
//   weights: [N, 63]
//   u      : [N, 128]
//   out    : [N, 128]
//
// R3: occupancy capped at 8 blocks/SM (regs<=32); bins staged as
// (b[i], b[i+1]) float2 pairs so the lerp endpoints are ONE LDS.64 gather;
// search levels 32/16/8 stay in warp-uniform registers (no LDS); bisection
// tracks cdf_lo/cdf_hi in registers. LDS per sample: 3 probes + 1 pair.

#define N_BINS 64
#define N_W    63
#define N_IMP  128
#define WARPS_PER_BLOCK 8
#define THREADS (WARPS_PER_BLOCK * 32)

__global__ __launch_bounds__(THREADS, 8)
void sample_pdf_kernel(const float* __restrict__ bins,
                       const float* __restrict__ weights,
                       const float* __restrict__ u,
                       float* __restrict__ out,
                       int n_rays)
{
    __shared__ float  s_cdf [WARPS_PER_BLOCK][N_BINS];
    __shared__ float2 s_pair[WARPS_PER_BLOCK][N_BINS];

    const int warp = threadIdx.x >> 5;
    const int lane = threadIdx.x & 31;
    const int ray  = blockIdx.x * WARPS_PER_BLOCK + warp;
    if (ray >= n_rays) return;

    // ---- issue all global loads up front (overlap with scan) --------------
    const float* wrow = weights + (long long)ray * N_W;
    const int l2 = lane * 2;
    const float wa = wrow[l2] + 1e-5f;
    const float wb = (l2 + 1 < N_W) ? wrow[l2 + 1] + 1e-5f : 0.0f;
    const float2 bv  = ((const float2*)(bins + (long long)ray * N_BINS))[lane];
    const float4 uv4 = ((const float4*)(u    + (long long)ray * N_IMP ))[lane];

    // ---- 32-wide inclusive scan of pair sums ------------------------------
    float P = wa + wb;
    #pragma unroll
    for (int d = 1; d < 32; d <<= 1) {
        float t = __shfl_up_sync(0xffffffffu, P, d);
        if (lane >= d) P += t;
    }
    const float total = __shfl_sync(0xffffffffu, P, 31);
    const float inv   = 1.0f / total;

    // warp-uniform CDF values for register search levels (even indices:
    // cdf[2k+2] = P[k]*inv)
    const float cdf8  = __shfl_sync(0xffffffffu, P,  3) * inv;
    const float cdf16 = __shfl_sync(0xffffffffu, P,  7) * inv;
    const float cdf24 = __shfl_sync(0xffffffffu, P, 11) * inv;
    const float cdf32 = __shfl_sync(0xffffffffu, P, 15) * inv;
    const float cdf40 = __shfl_sync(0xffffffffu, P, 19) * inv;
    const float cdf48 = __shfl_sync(0xffffffffu, P, 23) * inv;
    const float cdf56 = __shfl_sync(0xffffffffu, P, 27) * inv;
    const float cdf63 = total * inv;

    // ---- cdf in shared: cdf[2l+1]=(P-wb)*inv, cdf[2l+2]=P*inv -------------
    float* cdfw = s_cdf[warp];
    if (lane == 0) cdfw[0] = 0.0f;
    cdfw[l2 + 1] = (P - wb) * inv;
    if (l2 + 2 < N_BINS) cdfw[l2 + 2] = P * inv;

    // ---- bins as pairs: pair[i] = (b[i], b[i+1]), pair[63]=(b63,b63) ------
    float2* prw = s_pair[warp];
    float bnext = __shfl_down_sync(0xffffffffu, bv.x, 1);  // b[2l+2]
    if (lane == 31) bnext = bv.y;                          // clamp for pair[63]
    prw[l2]     = make_float2(bv.x, bv.y);
    prw[l2 + 1] = make_float2(bv.y, bnext);

    __syncwarp();

    // ---- 4 samples per lane -----------------------------------------------
    const float uvs[4] = {uv4.x, uv4.y, uv4.z, uv4.w};
    float res[4];

    #pragma unroll
    for (int k = 0; k < 4; ++k) {
        const float uv = uvs[k];
        int   idx = 0;
        float lov = 0.0f;
        float hiv = cdf63;

        // levels 32/16/8: warp-uniform registers, zero LDS
        const bool c1 = cdf32 < uv;
        if (c1) { idx = 32; lov = cdf32; } else { hiv = cdf32; }
        const float p2 = c1 ? cdf48 : cdf16;
        const bool  c2 = p2 < uv;
        if (c2) { idx += 16; lov = p2; } else { hiv = p2; }
        const float p3 = c1 ? (c2 ? cdf56 : cdf40) : (c2 ? cdf24 : cdf8);
        const bool  c3 = p3 < uv;
        if (c3) { idx += 8; lov = p3; } else { hiv = p3; }

        // levels 4/2/1: shared probes
        #pragma unroll
        for (int step = 4; step > 0; step >>= 1) {
            const float v = cdfw[idx + step];
            if (v < uv) { idx += step; lov = v; } else { hiv = v; }
        }
        // lov = cdf[idx], hiv = cdf[idx+1] (or cdf63 at the top edge)

        const float2 bp = prw[idx];          // (bins[idx], bins[idx+1])

        float denom = hiv - lov;
        denom = (denom < 1e-5f) ? 1.0f : denom;
        const float t = (uv - lov) / denom;
        res[k] = fmaf(t, bp.y - bp.x, bp.x);
    }

    float4 o;
    o.x = res[0]; o.y = res[1]; o.z = res[2]; o.w = res[3];
    ((float4*)(out + (long long)ray * N_IMP))[lane] = o;
}

extern "C" void kernel_launch(void* const* d_in, const int* in_sizes, int n_in,
                              void* d_out, int out_size)
{
    const float* bins    = (const float*)d_in[0];
    const float* weights = (const float*)d_in[1];
    const float* u       = (const float*)d_in[2];
    float* out = (float*)d_out;

    const int n_rays = in_sizes[0] / N_BINS;
    const int grid   = (n_rays + WARPS_PER_BLOCK - 1) / WARPS_PER_BLOCK;
    sample_pdf_kernel<<<grid, THREADS>>>(bins, weights, u, out, n_rays);
}

// round 4
// speedup vs baseline: 1.3566x; 1.0078x over previous
#include <cuda_runtime.h>
#include <cuda_bf16.h>

// SamplePDF: inverse-transform sampling, one warp per ray.
//   bins   : [N, 64]  sorted bin edges
//   weights: [N, 63]
//   u      : [N, 128]
//   out    : [N, 128]
//
// R4: ZERO shared memory. The pair-scan leaves the full CDF distributed in
// registers (lane m: cdf[2m+1], cdf[2m+2]); bins likewise (b[2m], b[2m+1]).
// Search levels 32/16/8 use warp-uniform register selects; levels 4/2/1 and
// the bin-endpoint fetch use lane-indexed __shfl_sync (conflict-free).
// L1TEX carries only the 12 coalesced global wavefronts per warp.

#define N_BINS 64
#define N_W    63
#define N_IMP  128
#define WARPS_PER_BLOCK 8
#define THREADS (WARPS_PER_BLOCK * 32)
#define FULL 0xffffffffu

__global__ __launch_bounds__(THREADS, 6)
void sample_pdf_kernel(const float* __restrict__ bins,
                       const float* __restrict__ weights,
                       const float* __restrict__ u,
                       float* __restrict__ out,
                       int n_rays)
{
    const int warp = threadIdx.x >> 5;
    const int lane = threadIdx.x & 31;
    const int ray  = blockIdx.x * WARPS_PER_BLOCK + warp;
    if (ray >= n_rays) return;

    // ---- global loads up front (coalesced / vectorized) -------------------
    const float* wrow = weights + (long long)ray * N_W;
    const int l2 = lane * 2;
    const float wa = wrow[l2] + 1e-5f;                       // w[2m]
    const float wb = (l2 + 1 < N_W) ? wrow[l2 + 1] + 1e-5f : 0.0f; // w[2m+1]
    const float2 bv  = ((const float2*)(bins + (long long)ray * N_BINS))[lane];
    const float4 uv4 = ((const float4*)(u    + (long long)ray * N_IMP ))[lane];

    // ---- 32-wide inclusive scan of pair sums ------------------------------
    float P = wa + wb;
    #pragma unroll
    for (int d = 1; d < 32; d <<= 1) {
        float t = __shfl_up_sync(FULL, P, d);
        if (lane >= d) P += t;
    }
    const float total = __shfl_sync(FULL, P, 31);
    const float inv   = 1.0f / total;

    // distributed CDF in registers:
    //   evenv[m] = cdf[2m+2],  oddv[m] = cdf[2m+1]
    const float evenv = P * inv;
    const float oddv  = (P - wb) * inv;

    // warp-uniform values for register search levels (cdf[2k+2] = P[k]*inv)
    const float cdf8  = __shfl_sync(FULL, evenv,  3);
    const float cdf16 = __shfl_sync(FULL, evenv,  7);
    const float cdf24 = __shfl_sync(FULL, evenv, 11);
    const float cdf32 = __shfl_sync(FULL, evenv, 15);
    const float cdf40 = __shfl_sync(FULL, evenv, 19);
    const float cdf48 = __shfl_sync(FULL, evenv, 23);
    const float cdf56 = __shfl_sync(FULL, evenv, 27);
    const float cdf63 = __shfl_sync(FULL, oddv,  31);

    // distributed bins in registers: bv.x = b[2m], bv.y = b[2m+1]

    // ---- 4 samples per lane -----------------------------------------------
    const float uvs[4] = {uv4.x, uv4.y, uv4.z, uv4.w};
    float res[4];

    #pragma unroll
    for (int k = 0; k < 4; ++k) {
        const float uv = uvs[k];
        int   idx = 0;
        float lov = 0.0f;
        float hiv = cdf63;

        // levels 32/16/8: warp-uniform registers (pure ALU)
        const bool c1 = cdf32 < uv;
        if (c1) { idx = 32; lov = cdf32; } else { hiv = cdf32; }
        const float p2 = c1 ? cdf48 : cdf16;
        const bool  c2 = p2 < uv;
        if (c2) { idx += 16; lov = p2; } else { hiv = p2; }
        const float p3 = c1 ? (c2 ? cdf56 : cdf40) : (c2 ? cdf24 : cdf8);
        const bool  c3 = p3 < uv;
        if (c3) { idx += 8; lov = p3; } else { hiv = p3; }

        // level 4: probe cdf[idx+4] (even) = evenv[(idx+4)/2-1] = evenv[idx/2+1]
        const float p4 = __shfl_sync(FULL, evenv, (idx >> 1) + 1);
        if (p4 < uv) { idx += 4; lov = p4; } else { hiv = p4; }
        // level 2: probe cdf[idx+2] (even) = evenv[idx/2]
        const float p5 = __shfl_sync(FULL, evenv, idx >> 1);
        if (p5 < uv) { idx += 2; lov = p5; } else { hiv = p5; }
        // level 1: probe cdf[idx+1] (odd)  = oddv[idx/2]
        const float p6 = __shfl_sync(FULL, oddv, idx >> 1);
        if (p6 < uv) { idx += 1; lov = p6; } else { hiv = p6; }
        // invariant: lov = cdf[idx], hiv = cdf[idx+1] (cdf63 at top edge)

        // bins[idx], bins[idx+1] via 3 shuffles + parity selects
        const int  h   = idx >> 1;
        const bool odd = (idx & 1) != 0;
        const float ax  = __shfl_sync(FULL, bv.x, h);                 // b[2h]
        const float ay  = __shfl_sync(FULL, bv.y, h);                 // b[2h+1]
        const float ax1 = __shfl_sync(FULL, bv.x, (h < 31) ? h + 1 : 31); // b[2h+2]
        const float blo = odd ? ay : ax;
        float       bhi = odd ? ax1 : ay;
        if (idx == N_BINS - 1) bhi = ay;   // clamp: bins[64] -> bins[63]

        float denom = hiv - lov;
        denom = (denom < 1e-5f) ? 1.0f : denom;
        const float t = (uv - lov) / denom;
        res[k] = fmaf(t, bhi - blo, blo);
    }

    float4 o;
    o.x = res[0]; o.y = res[1]; o.z = res[2]; o.w = res[3];
    ((float4*)(out + (long long)ray * N_IMP))[lane] = o;
}

extern "C" void kernel_launch(void* const* d_in, const int* in_sizes, int n_in,
                              void* d_out, int out_size)
{
    const float* bins    = (const float*)d_in[0];
    const float* weights = (const float*)d_in[1];
    const float* u       = (const float*)d_in[2];
    float* out = (float*)d_out;

    const int n_rays = in_sizes[0] / N_BINS;
    const int grid   = (n_rays + WARPS_PER_BLOCK - 1) / WARPS_PER_BLOCK;
    sample_pdf_kernel<<<grid, THREADS>>>(bins, weights, u, out, n_rays);
}

// round 5
// speedup vs baseline: 1.4893x; 1.0978x over previous
#include <cuda_runtime.h>
#include <cuda_bf16.h>

// SamplePDF: inverse-transform sampling, one warp per ray, zero shared memory.
//   bins   : [N, 64]  sorted bin edges
//   weights: [N, 63]
//   u      : [N, 128]
//   out    : [N, 128]
//
// R5: slope precompute. denom_i = pdf_i is locally available per lane, so the
// per-sample division disappears: sample = fma(u - cdf_lo, slope[idx], b[idx]).
// Search tracks only (idx, lov); levels 32/16/8 via warp-uniform registers,
// levels 4/2/1 via parity-fixed shuffles of the register-distributed CDF.

#define N_BINS 64
#define N_W    63
#define N_IMP  128
#define WARPS_PER_BLOCK 8
#define THREADS (WARPS_PER_BLOCK * 32)
#define FULL 0xffffffffu

__global__ __launch_bounds__(THREADS, 8)
void sample_pdf_kernel(const float* __restrict__ bins,
                       const float* __restrict__ weights,
                       const float* __restrict__ u,
                       float* __restrict__ out,
                       int n_rays)
{
    const int warp = threadIdx.x >> 5;
    const int lane = threadIdx.x & 31;
    const int ray  = blockIdx.x * WARPS_PER_BLOCK + warp;
    if (ray >= n_rays) return;

    // ---- global loads up front (coalesced / vectorized) -------------------
    const float* wrow = weights + (long long)ray * N_W;
    const int l2 = lane * 2;
    const float wa = wrow[l2] + 1e-5f;                             // w[2m]
    const float wb = (l2 + 1 < N_W) ? wrow[l2 + 1] + 1e-5f : 0.0f; // w[2m+1]
    const float2 bv  = ((const float2*)(bins + (long long)ray * N_BINS))[lane];
    const float4 uv4 = ((const float4*)(u    + (long long)ray * N_IMP ))[lane];

    // ---- 32-wide inclusive scan of pair sums ------------------------------
    float P = wa + wb;
    #pragma unroll
    for (int d = 1; d < 32; d <<= 1) {
        float t = __shfl_up_sync(FULL, P, d);
        if (lane >= d) P += t;
    }
    const float total = __shfl_sync(FULL, P, 31);
    const float inv   = 1.0f / total;

    // distributed CDF in registers: evenv[m]=cdf[2m+2], oddv[m]=cdf[2m+1]
    const float evenv = P * inv;
    const float oddv  = (P - wb) * inv;

    // warp-uniform CDF values for register search levels
    const float cdf8  = __shfl_sync(FULL, evenv,  3);
    const float cdf16 = __shfl_sync(FULL, evenv,  7);
    const float cdf24 = __shfl_sync(FULL, evenv, 11);
    const float cdf32 = __shfl_sync(FULL, evenv, 15);
    const float cdf40 = __shfl_sync(FULL, evenv, 19);
    const float cdf48 = __shfl_sync(FULL, evenv, 23);
    const float cdf56 = __shfl_sync(FULL, evenv, 27);

    // ---- per-interval slope precompute (2 intervals per lane) -------------
    // denom_i = pdf_i (= cdf[i+1]-cdf[i] by construction), clamped to 1 if
    // < 1e-5 exactly like the reference. slope_i = (b[i+1]-b[i]) / denom_i.
    float bnext = __shfl_down_sync(FULL, bv.x, 1);   // b[2m+2]
    if (lane == 31) bnext = bv.y;                    // width[63] = 0 -> slope 0
    const float pa = wa * inv;
    const float pb = wb * inv;
    const float da = (pa < 1e-5f) ? 1.0f : pa;
    const float db = (pb < 1e-5f) ? 1.0f : pb;
    const float sav = (bv.y  - bv.x) / da;           // slope[2m]
    const float sbv = (bnext - bv.y) / db;           // slope[2m+1]

    // ---- 4 samples per lane -----------------------------------------------
    const float uvs[4] = {uv4.x, uv4.y, uv4.z, uv4.w};
    float res[4];

    #pragma unroll
    for (int k = 0; k < 4; ++k) {
        const float uv = uvs[k];
        int   idx = 0;
        float lov = 0.0f;

        // levels 32/16/8: warp-uniform registers (pure ALU)
        const bool c1 = cdf32 < uv;
        if (c1) { idx = 32; lov = cdf32; }
        const float p2 = c1 ? cdf48 : cdf16;
        const bool  c2 = p2 < uv;
        if (c2) { idx += 16; lov = p2; }
        const float p3 = c1 ? (c2 ? cdf56 : cdf40) : (c2 ? cdf24 : cdf8);
        const bool  c3 = p3 < uv;
        if (c3) { idx += 8; lov = p3; }

        // level 4: cdf[idx+4] (even) = evenv[idx/2 + 1]
        const float p4 = __shfl_sync(FULL, evenv, (idx >> 1) + 1);
        if (p4 < uv) { idx += 4; lov = p4; }
        // level 2: cdf[idx+2] (even) = evenv[idx/2]
        const float p5 = __shfl_sync(FULL, evenv, idx >> 1);
        if (p5 < uv) { idx += 2; lov = p5; }
        // level 1: cdf[idx+1] (odd)  = oddv[idx/2]
        const float p6 = __shfl_sync(FULL, oddv, idx >> 1);
        if (p6 < uv) { idx += 1; lov = p6; }
        // invariant: idx = largest i with cdf[i] < uv; lov = cdf[idx]

        // gather b[idx] and slope[idx] (parity select, 4 shuffles)
        const int  h   = idx >> 1;
        const bool odd = (idx & 1) != 0;
        const float bx = __shfl_sync(FULL, bv.x, h);   // b[2h]
        const float by = __shfl_sync(FULL, bv.y, h);   // b[2h+1]
        const float sA = __shfl_sync(FULL, sav,  h);   // slope[2h]
        const float sB = __shfl_sync(FULL, sbv,  h);   // slope[2h+1]
        const float blo   = odd ? by : bx;
        const float slope = odd ? sB : sA;

        res[k] = fmaf(uv - lov, slope, blo);
    }

    float4 o;
    o.x = res[0]; o.y = res[1]; o.z = res[2]; o.w = res[3];
    ((float4*)(out + (long long)ray * N_IMP))[lane] = o;
}

extern "C" void kernel_launch(void* const* d_in, const int* in_sizes, int n_in,
                              void* d_out, int out_size)
{
    const float* bins    = (const float*)d_in[0];
    const float* weights = (const float*)d_in[1];
    const float* u       = (const float*)d_in[2];
    float* out = (float*)d_out;

    const int n_rays = in_sizes[0] / N_BINS;
    const int grid   = (n_rays + WARPS_PER_BLOCK - 1) / WARPS_PER_BLOCK;
    sample_pdf_kernel<<<grid, THREADS>>>(bins, weights, u, out, n_rays);
}

// round 6
// speedup vs baseline: 1.5231x; 1.0227x over previous
#include <cuda_runtime.h>
#include <cuda_bf16.h>

// SamplePDF: inverse-transform sampling, one warp per ray, zero shared memory.
//   bins   : [N, 64]  sorted bin edges
//   weights: [N, 63]
//   u      : [N, 128]
//   out    : [N, 128]
//
// R6: intercept precompute. sample = u*slope[idx] + c[idx] with
// c_i = b_i - cdf[i]*slope_i (cdf[i] is lane-local!), so the binary search
// tracks ONLY idx -- no cdf_lo bookkeeping, no per-sample subtract.
// Levels 32/16/8: warp-uniform register selects. Levels 4/2/1: parity-fixed
// shuffles of the register-distributed CDF. Gather: 4 shuffles + 2 selects.

#define N_BINS 64
#define N_W    63
#define N_IMP  128
#define WARPS_PER_BLOCK 8
#define THREADS (WARPS_PER_BLOCK * 32)
#define FULL 0xffffffffu

__global__ __launch_bounds__(THREADS, 8)
void sample_pdf_kernel(const float* __restrict__ bins,
                       const float* __restrict__ weights,
                       const float* __restrict__ u,
                       float* __restrict__ out,
                       int n_rays)
{
    const int warp = threadIdx.x >> 5;
    const int lane = threadIdx.x & 31;
    const int ray  = blockIdx.x * WARPS_PER_BLOCK + warp;
    if (ray >= n_rays) return;

    // ---- global loads up front (coalesced / vectorized) -------------------
    const float* wrow = weights + (long long)ray * N_W;
    const int l2 = lane * 2;
    const float wa = wrow[l2] + 1e-5f;                             // w[2m]
    const float wb = (l2 + 1 < N_W) ? wrow[l2 + 1] + 1e-5f : 0.0f; // w[2m+1]
    const float2 bv  = ((const float2*)(bins + (long long)ray * N_BINS))[lane];
    const float4 uv4 = ((const float4*)(u    + (long long)ray * N_IMP ))[lane];

    // ---- 32-wide inclusive scan of pair sums ------------------------------
    const float pairsum = wa + wb;
    float P = pairsum;
    #pragma unroll
    for (int d = 1; d < 32; d <<= 1) {
        float t = __shfl_up_sync(FULL, P, d);
        if (lane >= d) P += t;
    }
    const float total = __shfl_sync(FULL, P, 31);
    const float inv   = 1.0f / total;

    // distributed CDF in registers: evenv[m]=cdf[2m+2], oddv[m]=cdf[2m+1]
    const float evenv = P * inv;
    const float oddv  = (P - wb) * inv;
    const float cdf2m = (P - pairsum) * inv;        // cdf[2m] (exclusive)

    // warp-uniform CDF values for register search levels
    const float cdf8  = __shfl_sync(FULL, evenv,  3);
    const float cdf16 = __shfl_sync(FULL, evenv,  7);
    const float cdf24 = __shfl_sync(FULL, evenv, 11);
    const float cdf32 = __shfl_sync(FULL, evenv, 15);
    const float cdf40 = __shfl_sync(FULL, evenv, 19);
    const float cdf48 = __shfl_sync(FULL, evenv, 23);
    const float cdf56 = __shfl_sync(FULL, evenv, 27);

    // ---- per-interval slope + intercept precompute (2 intervals/lane) -----
    // denom_i = pdf_i, clamped to 1 if < 1e-5 (exactly the reference rule).
    // slope_i = (b[i+1]-b[i]) / denom_i ;  c_i = b_i - cdf[i]*slope_i.
    float bnext = __shfl_down_sync(FULL, bv.x, 1);   // b[2m+2]
    if (lane == 31) bnext = bv.y;                    // width[63]=0 -> slope 0
    const float pa = wa * inv;
    const float pb = wb * inv;
    const float da = (pa < 1e-5f) ? 1.0f : pa;
    const float db = (pb < 1e-5f) ? 1.0f : pb;
    const float sav = (bv.y  - bv.x) / da;           // slope[2m]
    const float sbv = (bnext - bv.y) / db;           // slope[2m+1]
    const float cav = fmaf(-cdf2m, sav, bv.x);       // c[2m]
    const float cbv = fmaf(-oddv,  sbv, bv.y);       // c[2m+1]

    // ---- 4 samples per lane -----------------------------------------------
    const float uvs[4] = {uv4.x, uv4.y, uv4.z, uv4.w};
    float res[4];

    #pragma unroll
    for (int k = 0; k < 4; ++k) {
        const float uv = uvs[k];
        int idx = 0;

        // levels 32/16/8: warp-uniform registers (pure ALU)
        const bool c1 = cdf32 < uv;
        if (c1) idx = 32;
        const float p2 = c1 ? cdf48 : cdf16;
        const bool  c2 = p2 < uv;
        if (c2) idx += 16;
        const float p3 = c1 ? (c2 ? cdf56 : cdf40) : (c2 ? cdf24 : cdf8);
        if (p3 < uv) idx += 8;

        // level 4: cdf[idx+4] (even) = evenv[idx/2 + 1]
        const float p4 = __shfl_sync(FULL, evenv, (idx >> 1) + 1);
        if (p4 < uv) idx += 4;
        // level 2: cdf[idx+2] (even) = evenv[idx/2]
        const float p5 = __shfl_sync(FULL, evenv, idx >> 1);
        if (p5 < uv) idx += 2;
        // level 1: cdf[idx+1] (odd)  = oddv[idx/2]
        const float p6 = __shfl_sync(FULL, oddv, idx >> 1);
        if (p6 < uv) idx += 1;
        // idx = largest i with cdf[i] < uv  (0 if none)

        // gather slope[idx], c[idx] (4 shuffles + parity selects)
        const int  h   = idx >> 1;
        const bool odd = (idx & 1) != 0;
        const float sA = __shfl_sync(FULL, sav, h);
        const float sB = __shfl_sync(FULL, sbv, h);
        const float cA = __shfl_sync(FULL, cav, h);
        const float cB = __shfl_sync(FULL, cbv, h);
        const float slope = odd ? sB : sA;
        const float cval  = odd ? cB : cA;

        res[k] = fmaf(uv, slope, cval);
    }

    float4 o;
    o.x = res[0]; o.y = res[1]; o.z = res[2]; o.w = res[3];
    ((float4*)(out + (long long)ray * N_IMP))[lane] = o;
}

extern "C" void kernel_launch(void* const* d_in, const int* in_sizes, int n_in,
                              void* d_out, int out_size)
{
    const float* bins    = (const float*)d_in[0];
    const float* weights = (const float*)d_in[1];
    const float* u       = (const float*)d_in[2];
    float* out = (float*)d_out;

    const int n_rays = in_sizes[0] / N_BINS;
    const int grid   = (n_rays + WARPS_PER_BLOCK - 1) / WARPS_PER_BLOCK;
    sample_pdf_kernel<<<grid, THREADS>>>(bins, weights, u, out, n_rays);
}